// round 6
// baseline (speedup 1.0000x reference)
#include <cuda_runtime.h>
#include <cuda_bf16.h>

// Table-batched EmbeddingBag forward (SUM pooling).
// T=8 tables, B=8192 batch, D=128 dim, ROWS=200000 rows/table.
// One warp per bag; lane l owns one float4 of the D=128 row.
// Lane-parallel index prefetch + shfl broadcast -> 8 independent
// 512B row gathers in flight per warp (no per-iteration index dependency).

#ifndef EMB_T
#define EMB_T 8
#define EMB_B 8192
#define EMB_D 128
#define EMB_ROWS 200000
#endif

#define D4 (EMB_D / 4)   // float4 per row = 32

__device__ __forceinline__ void facc(float4& a, const float4& v) {
    a.x += v.x; a.y += v.y; a.z += v.z; a.w += v.w;
}

__global__ __launch_bounds__(256) void emb_bag_sum_kernel(
    const int* __restrict__ indices,
    const int* __restrict__ offsets,
    const float4* __restrict__ weights4,
    float4* __restrict__ out4,
    int n_bags)
{
    const int warp_id = (blockIdx.x * blockDim.x + threadIdx.x) >> 5;
    const int lane    = threadIdx.x & 31;
    if (warp_id >= n_bags) return;

    const unsigned FULL = 0xffffffffu;

    const int bag     = warp_id;
    const int feature = bag / EMB_B;
    const int b       = bag - feature * EMB_B;

    const int start = __ldg(offsets + bag);
    const int end   = __ldg(offsets + bag + 1);
    const int n     = end - start;
    const int m     = n < 32 ? n : 32;

    // table base (in float4 units)
    const float4* __restrict__ tbl =
        weights4 + (size_t)feature * EMB_ROWS * D4 + lane;

    // Lane-parallel index prefetch (one coalesced transaction for the bag).
    int myidx = 0;
    if (lane < m) myidx = __ldg(indices + start + lane);

    float4 a0 = make_float4(0.f, 0.f, 0.f, 0.f);
    float4 a1 = make_float4(0.f, 0.f, 0.f, 0.f);

    int j = 0;
    // 8 independent gathers in flight per iteration.
    for (; j + 8 <= m; j += 8) {
        const int r0 = __shfl_sync(FULL, myidx, j + 0);
        const int r1 = __shfl_sync(FULL, myidx, j + 1);
        const int r2 = __shfl_sync(FULL, myidx, j + 2);
        const int r3 = __shfl_sync(FULL, myidx, j + 3);
        const int r4 = __shfl_sync(FULL, myidx, j + 4);
        const int r5 = __shfl_sync(FULL, myidx, j + 5);
        const int r6 = __shfl_sync(FULL, myidx, j + 6);
        const int r7 = __shfl_sync(FULL, myidx, j + 7);

        const float4 v0 = __ldg(tbl + (size_t)r0 * D4);
        const float4 v1 = __ldg(tbl + (size_t)r1 * D4);
        const float4 v2 = __ldg(tbl + (size_t)r2 * D4);
        const float4 v3 = __ldg(tbl + (size_t)r3 * D4);
        const float4 v4 = __ldg(tbl + (size_t)r4 * D4);
        const float4 v5 = __ldg(tbl + (size_t)r5 * D4);
        const float4 v6 = __ldg(tbl + (size_t)r6 * D4);
        const float4 v7 = __ldg(tbl + (size_t)r7 * D4);

        facc(a0, v0); facc(a1, v1); facc(a0, v2); facc(a1, v3);
        facc(a0, v4); facc(a1, v5); facc(a0, v6); facc(a1, v7);
    }
    // Remainder within first 32 indices (e.g. 20 = 8+8+4).
    for (; j < m; ++j) {
        const int r = __shfl_sync(FULL, myidx, j);
        const float4 v = __ldg(tbl + (size_t)r * D4);
        facc(a0, v);
    }
    // Generic ragged tail (bags longer than 32 — not hit for L=20).
    for (int k = 32; k < n; ++k) {
        const int r = __ldg(indices + start + k);
        const float4 v = __ldg(tbl + (size_t)r * D4);
        facc(a1, v);
    }

    facc(a0, a1);

    const size_t o = (size_t)b * (EMB_T * D4) + (size_t)feature * D4 + lane;
    out4[o] = a0;
}

extern "C" void kernel_launch(void* const* d_in, const int* in_sizes, int n_in,
                              void* d_out, int out_size)
{
    const int*   indices = (const int*)d_in[0];
    const int*   offsets = (const int*)d_in[1];
    const float* weights = (const float*)d_in[2];

    const int n_bags = in_sizes[1] - 1;      // T*B
    const int warps_per_block = 256 / 32;
    const int blocks = (n_bags + warps_per_block - 1) / warps_per_block;

    emb_bag_sum_kernel<<<blocks, 256>>>(
        indices, offsets,
        (const float4*)weights, (float4*)d_out, n_bags);
}